// round 4
// baseline (speedup 1.0000x reference)
#include <cuda_runtime.h>

// Problem dims (fixed per dataset)
#define B_    2
#define Q_    900
#define BQ    (B_*Q_)          // 1800
#define C_    256
#define NCAM  6
#define HF    112
#define WF    200
#define ZD    10
#define YD    128
#define XD    128
#define TQ    16               // queries per block in fuse kernel

typedef unsigned long long ull;

// Packed fp32x2 helpers (Blackwell PTX ISA 8.6)
__device__ __forceinline__ void fma2(ull& acc, ull a, ull b) {
    asm("fma.rn.f32x2 %0, %1, %2, %0;" : "+l"(acc) : "l"(a), "l"(b));
}
__device__ __forceinline__ ull pack2(float lo, float hi) {
    ull r; asm("mov.b64 %0, {%1,%2};" : "=l"(r) : "f"(lo), "f"(hi)); return r;
}
__device__ __forceinline__ float hsum2(ull v) {
    float lo, hi; asm("mov.b64 {%0,%1}, %2;" : "=f"(lo), "=f"(hi) : "l"(v));
    return lo + hi;
}

// Scratch (device globals: allocation-free rule)
__device__ float g_feat_cam[BQ * C_];
__device__ float g_feat_lid[BQ * C_];

// ---------------------------------------------------------------------------
// Kernel 1: per-query sampling. One block per (b,q), 256 threads = channels.
// ---------------------------------------------------------------------------
__global__ void sample_kernel(const float* __restrict__ rp,
                              const float* __restrict__ img,
                              const float* __restrict__ lid,
                              const float* __restrict__ l2i) {
    int bq = blockIdx.x;
    int b  = bq / Q_;
    int c  = threadIdx.x;

    __shared__ int   s_off[NCAM][4];
    __shared__ float s_w[NCAM][4];
    __shared__ int   s_valid[NCAM];
    __shared__ int   s_loff[8];
    __shared__ float s_lw[8];
    __shared__ float s_rcnt;

    if (threadIdx.x < NCAM) {
        int n = threadIdx.x;
        float rx = rp[bq*3+0], ry = rp[bq*3+1], rz = rp[bq*3+2];
        float ax = rx * 102.4f - 51.2f;
        float ay = ry * 102.4f - 51.2f;
        float az = rz * 8.0f   - 5.0f;
        const float* M = l2i + ((size_t)b * NCAM + n) * 16;
        float c0 = M[0]*ax + M[1]*ay + M[2]*az  + M[3];
        float c1 = M[4]*ax + M[5]*ay + M[6]*az  + M[7];
        float c2 = M[8]*ax + M[9]*ay + M[10]*az + M[11];
        bool  dmask = c2 > 1e-5f;
        float dc = fmaxf(c2, 1e-5f);
        float u = 2.0f * (c0 / dc) / 1599.0f - 1.0f;   // (W0-1)
        float v = 2.0f * (c1 / dc) / 899.0f  - 1.0f;   // (H0-1)
        bool valid = (u >= -1.0f) && (u <= 1.0f) && (v >= -1.0f) && (v <= 1.0f) && dmask;
        s_valid[n] = valid ? 1 : 0;
        if (valid) {
            float x = ((u + 1.0f) * (float)WF - 1.0f) * 0.5f;
            float y = ((v + 1.0f) * (float)HF - 1.0f) * 0.5f;
            float x0f = floorf(x), y0f = floorf(y);
            int   x0 = (int)x0f,  y0 = (int)y0f;
            float fx = x - x0f,   fy = y - y0f;
            float wx[2] = {1.0f - fx, fx};
            float wy[2] = {1.0f - fy, fy};
            #pragma unroll
            for (int dy = 0; dy < 2; dy++)
            #pragma unroll
            for (int dx = 0; dx < 2; dx++) {
                int xi = x0 + dx, yi = y0 + dy;
                bool inb = (xi >= 0) && (xi < WF) && (yi >= 0) && (yi < HF);
                s_off[n][dy*2+dx] = inb ? (yi * WF + xi) : -1;
                s_w[n][dy*2+dx]   = wx[dx] * wy[dy];
            }
        }
    }
    if (threadIdx.x == 32) {
        float rx = rp[bq*3+0], ry = rp[bq*3+1], rz = rp[bq*3+2];
        float gx = rx * 2.0f - 1.0f, gy = ry * 2.0f - 1.0f, gz = rz * 2.0f - 1.0f;
        float x = ((gx + 1.0f) * (float)XD - 1.0f) * 0.5f;
        float y = ((gy + 1.0f) * (float)YD - 1.0f) * 0.5f;
        float z = ((gz + 1.0f) * (float)ZD - 1.0f) * 0.5f;
        float x0f = floorf(x), y0f = floorf(y), z0f = floorf(z);
        int   x0 = (int)x0f,  y0 = (int)y0f,  z0 = (int)z0f;
        float fx = x - x0f,   fy = y - y0f,   fz = z - z0f;
        float wx[2] = {1.0f - fx, fx};
        float wy[2] = {1.0f - fy, fy};
        float wz[2] = {1.0f - fz, fz};
        #pragma unroll
        for (int dz = 0; dz < 2; dz++)
        #pragma unroll
        for (int dy = 0; dy < 2; dy++)
        #pragma unroll
        for (int dx = 0; dx < 2; dx++) {
            int xi = x0 + dx, yi = y0 + dy, zi = z0 + dz;
            bool inb = (xi >= 0) && (xi < XD) && (yi >= 0) && (yi < YD) && (zi >= 0) && (zi < ZD);
            int k = dz*4 + dy*2 + dx;
            s_loff[k] = inb ? ((zi * YD + yi) * XD + xi) : -1;
            s_lw[k]   = wx[dx] * wy[dy] * wz[dz];
        }
    }
    __syncthreads();
    if (threadIdx.x == 0) {
        int cnt = 0;
        #pragma unroll
        for (int n = 0; n < NCAM; n++) cnt += s_valid[n];
        s_rcnt = 1.0f / fmaxf((float)cnt, 1.0f);
    }
    __syncthreads();

    // camera branch: masked mean over valid cams
    float acc = 0.0f;
    #pragma unroll
    for (int n = 0; n < NCAM; n++) {
        if (s_valid[n]) {
            const float* p = img + (((size_t)(b * NCAM + n) * C_ + c) * (size_t)(HF * WF));
            #pragma unroll
            for (int j = 0; j < 4; j++) {
                int o = s_off[n][j];
                if (o >= 0) acc += s_w[n][j] * __ldg(p + o);
            }
        }
    }
    g_feat_cam[bq * C_ + c] = acc * s_rcnt;

    // lidar branch: trilinear
    const float* pl = lid + (((size_t)b * C_ + c) * (size_t)(ZD * YD * XD));
    float lacc = 0.0f;
    #pragma unroll
    for (int j = 0; j < 8; j++) {
        int o = s_loff[j];
        if (o >= 0) lacc += s_lw[j] * __ldg(pl + o);
    }
    g_feat_lid[bq * C_ + c] = lacc;
}

// ---------------------------------------------------------------------------
// Kernel 2: fused MLP chain. One block per TQ queries, 256 threads,
// 2 blocks/SM. Matvecs use packed f32x2 FMA (even/odd-k partial sums).
// ---------------------------------------------------------------------------
__global__ void __launch_bounds__(256, 2)
fuse_kernel(const float* __restrict__ query,
            const float* __restrict__ cam_w,  const float* __restrict__ cam_b,
            const float* __restrict__ lid_w,  const float* __restrict__ lid_b,
            const float* __restrict__ aw1,    const float* __restrict__ ab1,
            const float* __restrict__ aw2,    const float* __restrict__ ab2,
            const float* __restrict__ fw1,    const float* __restrict__ fb1,
            const float* __restrict__ lng,    const float* __restrict__ lnb,
            const float* __restrict__ fw2,    const float* __restrict__ fb2,
            float* __restrict__ out) {
    extern __shared__ float sm[];
    float* sCam = sm;                 // TQ*256  (later reused as h2)
    float* sLid = sCam + TQ*C_;       // TQ*256
    float* sQ   = sLid + TQ*C_;       // TQ*256  (later reused as t1)
    float* sFC  = sQ   + TQ*C_;       // TQ*256  gated cam projection
    float* sFL  = sFC  + TQ*C_;       // TQ*256  gated lidar projection
    float* sH   = sFL  + TQ*C_;       // TQ*64
    float* sWt  = sH   + TQ*64;       // TQ*2
    float* sRed = sWt  + TQ*2;        // TQ*16
    __shared__ float sMu[TQ], sRstd[TQ];

    int qbase = blockIdx.x * TQ;
    int nq = BQ - qbase; if (nq > TQ) nq = TQ;
    int t = threadIdx.x;

    // Vectorized activation staging (all spans are multiples of 4 floats).
    {
        const float4* gc = (const float4*)(g_feat_cam + qbase * C_);
        const float4* gl = (const float4*)(g_feat_lid + qbase * C_);
        const float4* gq = (const float4*)(query + qbase * C_);
        float4* c4 = (float4*)sCam;
        float4* l4 = (float4*)sLid;
        float4* q4 = (float4*)sQ;
        int nvec = nq * C_ / 4;
        for (int i = t; i < nvec; i += 256) {
            c4[i] = gc[i]; l4[i] = gl[i]; q4[i] = gq[i];
        }
        float4 z = make_float4(0.f, 0.f, 0.f, 0.f);
        for (int i = nvec + t; i < TQ * C_ / 4; i += 256) {
            c4[i] = z; l4[i] = z; q4[i] = z;
        }
    }
    __syncthreads();

    // Stage B: h = relu(sQ @ aw1 + ab1)  (TQ x 64; 4 q per thread)
    {
        int j  = t & 63;
        int q0 = (t >> 6) * 4;
        ull acc[4] = {0, 0, 0, 0};
        for (int k = 0; k < C_; k += 2) {
            ull w2 = pack2(aw1[k * 64 + j], aw1[(k + 1) * 64 + j]);
            #pragma unroll
            for (int i = 0; i < 4; i++) {
                ull a2 = *(const ull*)&sQ[(q0 + i) * C_ + k];
                fma2(acc[i], a2, w2);
            }
        }
        float bb = ab1[j];
        #pragma unroll
        for (int i = 0; i < 4; i++)
            sH[(q0 + i) * 64 + j] = fmaxf(hsum2(acc[i]) + bb, 0.0f);
    }
    __syncthreads();

    // Stage C: logits + 2-way softmax gate
    if (t < TQ) {
        int q = t;
        float l0 = ab2[0], l1 = ab2[1];
        for (int k = 0; k < 64; k++) {
            float h = sH[q * 64 + k];
            l0 += h * aw2[k * 2 + 0];
            l1 += h * aw2[k * 2 + 1];
        }
        float m  = fmaxf(l0, l1);
        float e0 = expf(l0 - m), e1 = expf(l1 - m);
        float s  = e0 + e1;
        sWt[q * 2 + 0] = e0 / s;
        sWt[q * 2 + 1] = e1 / s;
    }
    __syncthreads();

    // Stage A: gated projections (gate folded into the store)
    // sFC = w0 * (sCam @ cam_w + cam_b) ; sFL = w1 * (sLid @ lid_w + lid_b)
    {
        int j = t;
        {   // camera
            ull acc[TQ];
            #pragma unroll
            for (int q = 0; q < TQ; q++) acc[q] = 0;
            for (int k = 0; k < C_; k += 2) {
                ull w2 = pack2(cam_w[k * C_ + j], cam_w[(k + 1) * C_ + j]);
                #pragma unroll
                for (int q = 0; q < TQ; q++) {
                    ull a2 = *(const ull*)&sCam[q * C_ + k];
                    fma2(acc[q], a2, w2);
                }
            }
            float bb = cam_b[j];
            #pragma unroll
            for (int q = 0; q < TQ; q++)
                sFC[q * C_ + j] = sWt[q * 2 + 0] * (hsum2(acc[q]) + bb);
        }
        {   // lidar
            ull acc[TQ];
            #pragma unroll
            for (int q = 0; q < TQ; q++) acc[q] = 0;
            for (int k = 0; k < C_; k += 2) {
                ull w2 = pack2(lid_w[k * C_ + j], lid_w[(k + 1) * C_ + j]);
                #pragma unroll
                for (int q = 0; q < TQ; q++) {
                    ull a2 = *(const ull*)&sLid[q * C_ + k];
                    fma2(acc[q], a2, w2);
                }
            }
            float bb = lid_b[j];
            #pragma unroll
            for (int q = 0; q < TQ; q++)
                sFL[q * C_ + j] = sWt[q * 2 + 1] * (hsum2(acc[q]) + bb);
        }
    }
    __syncthreads();

    // Stage E: t1 = [sFC, sFL] @ fw1 + fb1 -> sQ (reuse)
    {
        int j = t;
        ull acc[TQ];
        #pragma unroll
        for (int q = 0; q < TQ; q++) acc[q] = 0;
        for (int k = 0; k < C_; k += 2) {
            ull w2 = pack2(fw1[k * C_ + j], fw1[(k + 1) * C_ + j]);
            #pragma unroll
            for (int q = 0; q < TQ; q++) {
                ull a2 = *(const ull*)&sFC[q * C_ + k];
                fma2(acc[q], a2, w2);
            }
        }
        for (int k = 0; k < C_; k += 2) {
            ull w2 = pack2(fw1[(C_ + k) * C_ + j], fw1[(C_ + k + 1) * C_ + j]);
            #pragma unroll
            for (int q = 0; q < TQ; q++) {
                ull a2 = *(const ull*)&sFL[q * C_ + k];
                fma2(acc[q], a2, w2);
            }
        }
        float bb = fb1[j];
        #pragma unroll
        for (int q = 0; q < TQ; q++) sQ[q * C_ + j] = hsum2(acc[q]) + bb;
    }
    __syncthreads();

    // Stage F: LayerNorm(t1) + relu -> sCam (reuse)
    {
        int q = t >> 4, lane = t & 15;
        float s = 0.0f;
        #pragma unroll
        for (int i = 0; i < 16; i++) s += sQ[q * C_ + lane * 16 + i];
        sRed[q * 16 + lane] = s;
    }
    __syncthreads();
    if (t < TQ) {
        float s = 0.0f;
        #pragma unroll
        for (int i = 0; i < 16; i++) s += sRed[t * 16 + i];
        sMu[t] = s * (1.0f / 256.0f);
    }
    __syncthreads();
    {
        int q = t >> 4, lane = t & 15;
        float mu = sMu[q];
        float s = 0.0f;
        #pragma unroll
        for (int i = 0; i < 16; i++) {
            float d = sQ[q * C_ + lane * 16 + i] - mu;
            s += d * d;
        }
        sRed[q * 16 + lane] = s;
    }
    __syncthreads();
    if (t < TQ) {
        float s = 0.0f;
        #pragma unroll
        for (int i = 0; i < 16; i++) s += sRed[t * 16 + i];
        sRstd[t] = rsqrtf(s * (1.0f / 256.0f) + 1e-5f);
    }
    __syncthreads();
    {
        int j = t;
        float g = lng[j], bb = lnb[j];
        #pragma unroll
        for (int q = 0; q < TQ; q++) {
            float v = (sQ[q * C_ + j] - sMu[q]) * sRstd[q] * g + bb;
            sCam[q * C_ + j] = fmaxf(v, 0.0f);
        }
    }
    __syncthreads();

    // Stage G: out = h2 @ fw2 + fb2
    {
        int j = t;
        ull acc[TQ];
        #pragma unroll
        for (int q = 0; q < TQ; q++) acc[q] = 0;
        for (int k = 0; k < C_; k += 2) {
            ull w2 = pack2(fw2[k * C_ + j], fw2[(k + 1) * C_ + j]);
            #pragma unroll
            for (int q = 0; q < TQ; q++) {
                ull a2 = *(const ull*)&sCam[q * C_ + k];
                fma2(acc[q], a2, w2);
            }
        }
        float bb = fb2[j];
        for (int q = 0; q < nq; q++)
            out[(qbase + q) * C_ + j] = hsum2(acc[q]) + bb;
    }
}

// ---------------------------------------------------------------------------
extern "C" void kernel_launch(void* const* d_in, const int* in_sizes, int n_in,
                              void* d_out, int out_size) {
    const float* query = (const float*)d_in[0];
    const float* rp    = (const float*)d_in[1];
    const float* img   = (const float*)d_in[2];
    const float* lid   = (const float*)d_in[3];
    const float* l2i   = (const float*)d_in[4];
    const float* cam_w = (const float*)d_in[5];
    const float* cam_b = (const float*)d_in[6];
    const float* lid_w = (const float*)d_in[7];
    const float* lid_b = (const float*)d_in[8];
    const float* aw1   = (const float*)d_in[9];
    const float* ab1   = (const float*)d_in[10];
    const float* aw2   = (const float*)d_in[11];
    const float* ab2   = (const float*)d_in[12];
    const float* fw1   = (const float*)d_in[13];
    const float* fb1   = (const float*)d_in[14];
    const float* lng   = (const float*)d_in[15];
    const float* lnb   = (const float*)d_in[16];
    const float* fw2   = (const float*)d_in[17];
    const float* fb2   = (const float*)d_in[18];
    float* out = (float*)d_out;

    sample_kernel<<<BQ, 256>>>(rp, img, lid, l2i);

    size_t smem = (size_t)(TQ*C_*5 + TQ*64 + TQ*2 + TQ*16) * sizeof(float);
    cudaFuncSetAttribute(fuse_kernel, cudaFuncAttributeMaxDynamicSharedMemorySize, (int)smem);
    int nblk = (BQ + TQ - 1) / TQ;
    fuse_kernel<<<nblk, 256, smem>>>(query,
                                     cam_w, cam_b, lid_w, lid_b,
                                     aw1, ab1, aw2, ab2,
                                     fw1, fb1, lng, lnb, fw2, fb2,
                                     out);
}

// round 6
// speedup vs baseline: 1.9151x; 1.9151x over previous
#include <cuda_runtime.h>

// Problem dims (fixed per dataset)
#define B_    2
#define Q_    900
#define BQ    (B_*Q_)          // 1800
#define C_    256
#define NCAM  6
#define HF    112
#define WF    200
#define ZD    10
#define YD    128
#define XD    128

#define TQ    14               // queries per block (1800/14 -> 129 blocks, 1 wave)
#define QP    7                // query pairs
#define AST   14               // activation row stride (floats per k row)
#define NT    512
#define NBLK  ((BQ + TQ - 1) / TQ)

typedef unsigned long long ull;

__device__ __forceinline__ void fma2(ull& acc, ull a, ull b) {
    asm("fma.rn.f32x2 %0, %1, %2, %0;" : "+l"(acc) : "l"(a), "l"(b));
}
__device__ __forceinline__ ull add2(ull a, ull b) {
    ull r; asm("add.rn.f32x2 %0, %1, %2;" : "=l"(r) : "l"(a), "l"(b)); return r;
}
__device__ __forceinline__ ull packdup(float w) {
    ull r; asm("mov.b64 %0, {%1,%1};" : "=l"(r) : "f"(w)); return r;
}
__device__ __forceinline__ void unpack2(ull v, float& lo, float& hi) {
    asm("mov.b64 {%0,%1}, %2;" : "=f"(lo), "=f"(hi) : "l"(v));
}

// Scratch (device globals: allocation-free rule)
__device__ float g_feat_cam[BQ * C_];
__device__ float g_feat_lid[BQ * C_];

// ---------------------------------------------------------------------------
// Kernel 1: per-query sampling. One block per (b,q), 256 threads = channels.
// ---------------------------------------------------------------------------
__global__ void sample_kernel(const float* __restrict__ rp,
                              const float* __restrict__ img,
                              const float* __restrict__ lid,
                              const float* __restrict__ l2i) {
    int bq = blockIdx.x;
    int b  = bq / Q_;
    int c  = threadIdx.x;

    __shared__ int   s_off[NCAM][4];
    __shared__ float s_w[NCAM][4];
    __shared__ int   s_valid[NCAM];
    __shared__ int   s_loff[8];
    __shared__ float s_lw[8];
    __shared__ float s_rcnt;

    if (threadIdx.x < NCAM) {
        int n = threadIdx.x;
        float rx = rp[bq*3+0], ry = rp[bq*3+1], rz = rp[bq*3+2];
        float ax = rx * 102.4f - 51.2f;
        float ay = ry * 102.4f - 51.2f;
        float az = rz * 8.0f   - 5.0f;
        const float* M = l2i + ((size_t)b * NCAM + n) * 16;
        float c0 = M[0]*ax + M[1]*ay + M[2]*az  + M[3];
        float c1 = M[4]*ax + M[5]*ay + M[6]*az  + M[7];
        float c2 = M[8]*ax + M[9]*ay + M[10]*az + M[11];
        bool  dmask = c2 > 1e-5f;
        float dc = fmaxf(c2, 1e-5f);
        float u = 2.0f * (c0 / dc) / 1599.0f - 1.0f;
        float v = 2.0f * (c1 / dc) / 899.0f  - 1.0f;
        bool valid = (u >= -1.0f) && (u <= 1.0f) && (v >= -1.0f) && (v <= 1.0f) && dmask;
        s_valid[n] = valid ? 1 : 0;
        if (valid) {
            float x = ((u + 1.0f) * (float)WF - 1.0f) * 0.5f;
            float y = ((v + 1.0f) * (float)HF - 1.0f) * 0.5f;
            float x0f = floorf(x), y0f = floorf(y);
            int   x0 = (int)x0f,  y0 = (int)y0f;
            float fx = x - x0f,   fy = y - y0f;
            float wx[2] = {1.0f - fx, fx};
            float wy[2] = {1.0f - fy, fy};
            #pragma unroll
            for (int dy = 0; dy < 2; dy++)
            #pragma unroll
            for (int dx = 0; dx < 2; dx++) {
                int xi = x0 + dx, yi = y0 + dy;
                bool inb = (xi >= 0) && (xi < WF) && (yi >= 0) && (yi < HF);
                s_off[n][dy*2+dx] = inb ? (yi * WF + xi) : -1;
                s_w[n][dy*2+dx]   = wx[dx] * wy[dy];
            }
        }
    }
    if (threadIdx.x == 32) {
        float rx = rp[bq*3+0], ry = rp[bq*3+1], rz = rp[bq*3+2];
        float gx = rx * 2.0f - 1.0f, gy = ry * 2.0f - 1.0f, gz = rz * 2.0f - 1.0f;
        float x = ((gx + 1.0f) * (float)XD - 1.0f) * 0.5f;
        float y = ((gy + 1.0f) * (float)YD - 1.0f) * 0.5f;
        float z = ((gz + 1.0f) * (float)ZD - 1.0f) * 0.5f;
        float x0f = floorf(x), y0f = floorf(y), z0f = floorf(z);
        int   x0 = (int)x0f,  y0 = (int)y0f,  z0 = (int)z0f;
        float fx = x - x0f,   fy = y - y0f,   fz = z - z0f;
        float wx[2] = {1.0f - fx, fx};
        float wy[2] = {1.0f - fy, fy};
        float wz[2] = {1.0f - fz, fz};
        #pragma unroll
        for (int dz = 0; dz < 2; dz++)
        #pragma unroll
        for (int dy = 0; dy < 2; dy++)
        #pragma unroll
        for (int dx = 0; dx < 2; dx++) {
            int xi = x0 + dx, yi = y0 + dy, zi = z0 + dz;
            bool inb = (xi >= 0) && (xi < XD) && (yi >= 0) && (yi < YD) && (zi >= 0) && (zi < ZD);
            int k = dz*4 + dy*2 + dx;
            s_loff[k] = inb ? ((zi * YD + yi) * XD + xi) : -1;
            s_lw[k]   = wx[dx] * wy[dy] * wz[dz];
        }
    }
    __syncthreads();
    if (threadIdx.x == 0) {
        int cnt = 0;
        #pragma unroll
        for (int n = 0; n < NCAM; n++) cnt += s_valid[n];
        s_rcnt = 1.0f / fmaxf((float)cnt, 1.0f);
    }
    __syncthreads();

    float acc = 0.0f;
    #pragma unroll
    for (int n = 0; n < NCAM; n++) {
        if (s_valid[n]) {
            const float* p = img + (((size_t)(b * NCAM + n) * C_ + c) * (size_t)(HF * WF));
            #pragma unroll
            for (int jj = 0; jj < 4; jj++) {
                int o = s_off[n][jj];
                if (o >= 0) acc += s_w[n][jj] * __ldg(p + o);
            }
        }
    }
    g_feat_cam[bq * C_ + c] = acc * s_rcnt;

    const float* pl = lid + (((size_t)b * C_ + c) * (size_t)(ZD * YD * XD));
    float lacc = 0.0f;
    #pragma unroll
    for (int jj = 0; jj < 8; jj++) {
        int o = s_loff[jj];
        if (o >= 0) lacc += s_lw[jj] * __ldg(pl + o);
    }
    g_feat_lid[bq * C_ + c] = lacc;
}

// ---------------------------------------------------------------------------
// mv256: partial matvec over K=256 with smem-staged, register-prefetched
// weight chunks (8 chunks x 32 rows x 256 cols). Thread (j, kh) accumulates
// its 128 k rows into acc[QP] (query-pair packed f32x2).
// ---------------------------------------------------------------------------
__device__ __forceinline__ void mv256(const float* __restrict__ W,
                                      const float* __restrict__ sIn,
                                      float* __restrict__ wbuf,
                                      int j, int kh, int t, ull* acc)
{
    const float4* Wv = (const float4*)W;
    float4 r0 = Wv[t], r1 = Wv[512 + t], r2 = Wv[1024 + t], r3 = Wv[1536 + t];
    #pragma unroll 1
    for (int c = 0; c < 8; c++) {
        __syncthreads();                      // wbuf safe to overwrite
        ((float4*)wbuf)[t]        = r0;
        ((float4*)wbuf)[512 + t]  = r1;
        ((float4*)wbuf)[1024 + t] = r2;
        ((float4*)wbuf)[1536 + t] = r3;
        if (c < 7) {
            const float4* Wn = Wv + (size_t)(c + 1) * 2048;
            r0 = Wn[t]; r1 = Wn[512 + t]; r2 = Wn[1024 + t]; r3 = Wn[1536 + t];
        }
        __syncthreads();                      // wbuf visible
        int kbase = c * 32 + kh * 16;
        #pragma unroll
        for (int kk = 0; kk < 16; kk++) {
            float w = wbuf[(kh * 16 + kk) * 256 + j];
            ull w2 = packdup(w);
            const ull* ap = (const ull*)(sIn + (kbase + kk) * AST);
            #pragma unroll
            for (int qp = 0; qp < QP; qp++)
                fma2(acc[qp], ap[qp], w2);
        }
    }
}

// ---------------------------------------------------------------------------
// Kernel 2: fused MLP chain. 512 threads = 256 j-columns x 2 k-halves.
// Activations live in smem transposed [k][q] (stride AST).
// ---------------------------------------------------------------------------
__global__ void __launch_bounds__(NT, 1)
fuse_kernel(const float* __restrict__ query,
            const float* __restrict__ cam_w,  const float* __restrict__ cam_b,
            const float* __restrict__ lid_w,  const float* __restrict__ lid_b,
            const float* __restrict__ aw1,    const float* __restrict__ ab1,
            const float* __restrict__ aw2,    const float* __restrict__ ab2,
            const float* __restrict__ fw1,    const float* __restrict__ fb1,
            const float* __restrict__ lng,    const float* __restrict__ lnb,
            const float* __restrict__ fw2,    const float* __restrict__ fb2,
            float* __restrict__ out) {
    extern __shared__ float sm[];
    float* B0   = sm;                  // 3584 f : query -> t1
    float* B1   = B0 + C_*AST;         // 3584 f : cam   -> fl
    float* B2   = B1 + C_*AST;         // 3584 f : lid   -> h2
    float* B3   = B2 + C_*AST;         // 3584 f : fc
    float* wbuf = B3 + C_*AST;         // 8192 f : weight chunk (also gate partials)
    ull*   sPart = (ull*)(wbuf + 8192);      // 256*QP ull = 14336B
    float* sHid  = (float*)(sPart + 256*QP); // 64*AST floats
    __shared__ float sWt[TQ][2], sMu[TQ], sRstd[TQ];

    int t  = threadIdx.x;
    int j  = t & 255;
    int kh = t >> 8;
    int qbase = blockIdx.x * TQ;
    int nq = BQ - qbase; if (nq > TQ) nq = TQ;

    // Transposed staging: B0<-query, B1<-cam, B2<-lid ([q][k] -> [k][q])
    for (int i = t; i < nq * C_; i += NT) {
        int q = i >> 8, k = i & 255;
        B0[k*AST + q] = query[(size_t)(qbase+q)*C_ + k];
        B1[k*AST + q] = g_feat_cam[(qbase+q)*C_ + k];
        B2[k*AST + q] = g_feat_lid[(qbase+q)*C_ + k];
    }
    for (int i = nq * C_ + t; i < TQ * C_; i += NT) {
        int q = i >> 8, k = i & 255;
        B0[k*AST+q] = 0.f; B1[k*AST+q] = 0.f; B2[k*AST+q] = 0.f;
    }
    __syncthreads();

    // ---- gate: h = relu(Q @ aw1 + ab1); wt = softmax(h @ aw2 + ab2) ----
    {
        int j4 = t & 63, kh8 = t >> 6;   // 64 cols x 8 k-groups of 32
        ull h[QP];
        #pragma unroll
        for (int qp = 0; qp < QP; qp++) h[qp] = 0;
        for (int kk = 0; kk < 32; kk++) {
            int k = kh8 * 32 + kk;
            ull w2 = packdup(aw1[k*64 + j4]);
            const ull* ap = (const ull*)(B0 + k*AST);
            #pragma unroll
            for (int qp = 0; qp < QP; qp++) fma2(h[qp], ap[qp], w2);
        }
        ull* gred = (ull*)wbuf;
        #pragma unroll
        for (int qp = 0; qp < QP; qp++) gred[(kh8*64 + j4)*QP + qp] = h[qp];
    }
    __syncthreads();
    if (t < 64 * QP) {
        int jj = t / QP, qp = t % QP;
        ull* gred = (ull*)wbuf;
        ull s = gred[jj*QP + qp];
        #pragma unroll
        for (int g8 = 1; g8 < 8; g8++) s = add2(s, gred[(g8*64 + jj)*QP + qp]);
        float lo, hi; unpack2(s, lo, hi);
        float bb = ab1[jj];
        sHid[jj*AST + 2*qp]   = fmaxf(lo + bb, 0.f);
        sHid[jj*AST + 2*qp+1] = fmaxf(hi + bb, 0.f);
    }
    __syncthreads();
    if (t < TQ) {
        float l0 = ab2[0], l1 = ab2[1];
        for (int kk = 0; kk < 64; kk++) {
            float h = sHid[kk*AST + t];
            l0 += h * aw2[kk*2+0];
            l1 += h * aw2[kk*2+1];
        }
        float m  = fmaxf(l0, l1);
        float e0 = expf(l0 - m), e1 = expf(l1 - m);
        float den = e0 + e1;
        sWt[t][0] = e0 / den; sWt[t][1] = e1 / den;
    }
    // (mv256's internal barriers order sWt/gred before reuse)

    // ---- stage A cam: B3 = wt0 * (B1 @ cam_w + cam_b) ----
    {
        ull acc[QP];
        #pragma unroll
        for (int qp = 0; qp < QP; qp++) acc[qp] = 0;
        mv256(cam_w, B1, wbuf, j, kh, t, acc);
        if (kh == 1) {
            #pragma unroll
            for (int qp = 0; qp < QP; qp++) sPart[j*QP + qp] = acc[qp];
        }
        __syncthreads();
        if (kh == 0) {
            float bb = cam_b[j];
            #pragma unroll
            for (int qp = 0; qp < QP; qp++) {
                ull s = add2(acc[qp], sPart[j*QP + qp]);
                float lo, hi; unpack2(s, lo, hi);
                B3[j*AST + 2*qp]   = sWt[2*qp][0]   * (lo + bb);
                B3[j*AST + 2*qp+1] = sWt[2*qp+1][0] * (hi + bb);
            }
        }
    }
    // ---- stage A lid: B1 = wt1 * (B2 @ lid_w + lid_b) ----
    {
        ull acc[QP];
        #pragma unroll
        for (int qp = 0; qp < QP; qp++) acc[qp] = 0;
        mv256(lid_w, B2, wbuf, j, kh, t, acc);
        if (kh == 1) {
            #pragma unroll
            for (int qp = 0; qp < QP; qp++) sPart[j*QP + qp] = acc[qp];
        }
        __syncthreads();
        if (kh == 0) {
            float bb = lid_b[j];
            #pragma unroll
            for (int qp = 0; qp < QP; qp++) {
                ull s = add2(acc[qp], sPart[j*QP + qp]);
                float lo, hi; unpack2(s, lo, hi);
                B1[j*AST + 2*qp]   = sWt[2*qp][1]   * (lo + bb);
                B1[j*AST + 2*qp+1] = sWt[2*qp+1][1] * (hi + bb);
            }
        }
    }
    // ---- stage E: B0 = fc @ fw1[0:256] + fl @ fw1[256:512] + fb1 ----
    {
        ull acc[QP];
        #pragma unroll
        for (int qp = 0; qp < QP; qp++) acc[qp] = 0;
        mv256(fw1,            B3, wbuf, j, kh, t, acc);
        mv256(fw1 + 256*C_,   B1, wbuf, j, kh, t, acc);
        if (kh == 1) {
            #pragma unroll
            for (int qp = 0; qp < QP; qp++) sPart[j*QP + qp] = acc[qp];
        }
        __syncthreads();
        if (kh == 0) {
            float bb = fb1[j];
            #pragma unroll
            for (int qp = 0; qp < QP; qp++) {
                ull s = add2(acc[qp], sPart[j*QP + qp]);
                float lo, hi; unpack2(s, lo, hi);
                B0[j*AST + 2*qp]   = lo + bb;
                B0[j*AST + 2*qp+1] = hi + bb;
            }
        }
    }
    __syncthreads();   // B0 (t1) complete for all threads

    // ---- LayerNorm + relu: B2 = relu(LN(B0)) ----
    {
        int wid = t >> 5, lane = t & 31;
        if (wid < TQ) {
            float s = 0.f;
            #pragma unroll
            for (int i = 0; i < 8; i++) s += B0[(lane + i*32)*AST + wid];
            #pragma unroll
            for (int off = 16; off; off >>= 1) s += __shfl_xor_sync(~0u, s, off);
            float mu = s * (1.0f/256.0f);
            float v = 0.f;
            #pragma unroll
            for (int i = 0; i < 8; i++) {
                float d = B0[(lane + i*32)*AST + wid] - mu;
                v += d * d;
            }
            #pragma unroll
            for (int off = 16; off; off >>= 1) v += __shfl_xor_sync(~0u, v, off);
            if (lane == 0) { sMu[wid] = mu; sRstd[wid] = rsqrtf(v*(1.0f/256.0f) + 1e-5f); }
        }
    }
    __syncthreads();
    {
        int k0 = t & 255, qh = t >> 8;
        float g = lng[k0], bb = lnb[k0];
        #pragma unroll
        for (int q = qh*QP; q < qh*QP + QP; q++) {
            float v = (B0[k0*AST + q] - sMu[q]) * sRstd[q] * g + bb;
            B2[k0*AST + q] = fmaxf(v, 0.f);
        }
    }

    // ---- stage G: out = h2 @ fw2 + fb2 ----
    {
        ull acc[QP];
        #pragma unroll
        for (int qp = 0; qp < QP; qp++) acc[qp] = 0;
        mv256(fw2, B2, wbuf, j, kh, t, acc);
        if (kh == 1) {
            #pragma unroll
            for (int qp = 0; qp < QP; qp++) sPart[j*QP + qp] = acc[qp];
        }
        __syncthreads();
        if (kh == 0) {
            float bb = fb2[j];
            #pragma unroll
            for (int qp = 0; qp < QP; qp++) {
                ull s = add2(acc[qp], sPart[j*QP + qp]);
                float lo, hi; unpack2(s, lo, hi);
                int q0 = 2*qp;
                if (q0 < nq)     out[(size_t)(qbase+q0)*C_ + j]   = lo + bb;
                if (q0 + 1 < nq) out[(size_t)(qbase+q0+1)*C_ + j] = hi + bb;
            }
        }
    }
}

// ---------------------------------------------------------------------------
extern "C" void kernel_launch(void* const* d_in, const int* in_sizes, int n_in,
                              void* d_out, int out_size) {
    const float* query = (const float*)d_in[0];
    const float* rp    = (const float*)d_in[1];
    const float* img   = (const float*)d_in[2];
    const float* lid   = (const float*)d_in[3];
    const float* l2i   = (const float*)d_in[4];
    const float* cam_w = (const float*)d_in[5];
    const float* cam_b = (const float*)d_in[6];
    const float* lid_w = (const float*)d_in[7];
    const float* lid_b = (const float*)d_in[8];
    const float* aw1   = (const float*)d_in[9];
    const float* ab1   = (const float*)d_in[10];
    const float* aw2   = (const float*)d_in[11];
    const float* ab2   = (const float*)d_in[12];
    const float* fw1   = (const float*)d_in[13];
    const float* fb1   = (const float*)d_in[14];
    const float* lng   = (const float*)d_in[15];
    const float* lnb   = (const float*)d_in[16];
    const float* fw2   = (const float*)d_in[17];
    const float* fb2   = (const float*)d_in[18];
    float* out = (float*)d_out;

    sample_kernel<<<BQ, 256>>>(rp, img, lid, l2i);

    size_t smem = (size_t)(4*C_*AST + 8192) * sizeof(float)
                + (size_t)(256*QP) * sizeof(ull)
                + (size_t)(64*AST) * sizeof(float);
    cudaFuncSetAttribute(fuse_kernel, cudaFuncAttributeMaxDynamicSharedMemorySize, (int)smem);
    fuse_kernel<<<NBLK, NT, smem>>>(query,
                                    cam_w, cam_b, lid_w, lid_b,
                                    aw1, ab1, aw2, ab2,
                                    fw1, fb1, lng, lnb, fw2, fb2,
                                    out);
}

// round 8
// speedup vs baseline: 2.1577x; 1.1267x over previous
#include <cuda_runtime.h>

// Problem dims (fixed per dataset)
#define B_    2
#define Q_    900
#define BQ    (B_*Q_)          // 1800
#define C_    256
#define NCAM  6
#define HF    112
#define WF    200
#define ZD    10
#define YD    128
#define XD    128

#define TQ    14               // queries per block (1800/14 -> 129 blocks)
#define QP    7                // query pairs
#define AST   16               // activation row stride (floats; 64B -> 16B-aligned rows)
#define NT    512
#define NBLK  ((BQ + TQ - 1) / TQ)

typedef unsigned long long ull;

__device__ __forceinline__ void fma2(ull& acc, ull a, ull b) {
    asm("fma.rn.f32x2 %0, %1, %2, %0;" : "+l"(acc) : "l"(a), "l"(b));
}
__device__ __forceinline__ ull add2(ull a, ull b) {
    ull r; asm("add.rn.f32x2 %0, %1, %2;" : "=l"(r) : "l"(a), "l"(b)); return r;
}
__device__ __forceinline__ ull packdup(float w) {
    ull r; asm("mov.b64 %0, {%1,%1};" : "=l"(r) : "f"(w)); return r;
}
__device__ __forceinline__ void unpack2(ull v, float& lo, float& hi) {
    asm("mov.b64 {%0,%1}, %2;" : "=f"(lo), "=f"(hi) : "l"(v));
}

// Scratch (device globals: allocation-free rule)
__device__ float g_feat_cam[BQ * C_];
__device__ float g_feat_lid[BQ * C_];

// ---------------------------------------------------------------------------
// Kernel 1: per-query sampling. One block per (b,q), 256 threads = channels.
// ---------------------------------------------------------------------------
__global__ void sample_kernel(const float* __restrict__ rp,
                              const float* __restrict__ img,
                              const float* __restrict__ lid,
                              const float* __restrict__ l2i) {
    int bq = blockIdx.x;
    int b  = bq / Q_;
    int c  = threadIdx.x;

    __shared__ int   s_off[NCAM][4];
    __shared__ float s_w[NCAM][4];
    __shared__ int   s_valid[NCAM];
    __shared__ int   s_loff[8];
    __shared__ float s_lw[8];
    __shared__ float s_rcnt;

    if (threadIdx.x < NCAM) {
        int n = threadIdx.x;
        float rx = rp[bq*3+0], ry = rp[bq*3+1], rz = rp[bq*3+2];
        float ax = rx * 102.4f - 51.2f;
        float ay = ry * 102.4f - 51.2f;
        float az = rz * 8.0f   - 5.0f;
        const float* M = l2i + ((size_t)b * NCAM + n) * 16;
        float c0 = M[0]*ax + M[1]*ay + M[2]*az  + M[3];
        float c1 = M[4]*ax + M[5]*ay + M[6]*az  + M[7];
        float c2 = M[8]*ax + M[9]*ay + M[10]*az + M[11];
        bool  dmask = c2 > 1e-5f;
        float dc = fmaxf(c2, 1e-5f);
        float u = 2.0f * (c0 / dc) / 1599.0f - 1.0f;
        float v = 2.0f * (c1 / dc) / 899.0f  - 1.0f;
        bool valid = (u >= -1.0f) && (u <= 1.0f) && (v >= -1.0f) && (v <= 1.0f) && dmask;
        s_valid[n] = valid ? 1 : 0;
        if (valid) {
            float x = ((u + 1.0f) * (float)WF - 1.0f) * 0.5f;
            float y = ((v + 1.0f) * (float)HF - 1.0f) * 0.5f;
            float x0f = floorf(x), y0f = floorf(y);
            int   x0 = (int)x0f,  y0 = (int)y0f;
            float fx = x - x0f,   fy = y - y0f;
            float wx[2] = {1.0f - fx, fx};
            float wy[2] = {1.0f - fy, fy};
            #pragma unroll
            for (int dy = 0; dy < 2; dy++)
            #pragma unroll
            for (int dx = 0; dx < 2; dx++) {
                int xi = x0 + dx, yi = y0 + dy;
                bool inb = (xi >= 0) && (xi < WF) && (yi >= 0) && (yi < HF);
                s_off[n][dy*2+dx] = inb ? (yi * WF + xi) : -1;
                s_w[n][dy*2+dx]   = wx[dx] * wy[dy];
            }
        }
    }
    if (threadIdx.x == 32) {
        float rx = rp[bq*3+0], ry = rp[bq*3+1], rz = rp[bq*3+2];
        float gx = rx * 2.0f - 1.0f, gy = ry * 2.0f - 1.0f, gz = rz * 2.0f - 1.0f;
        float x = ((gx + 1.0f) * (float)XD - 1.0f) * 0.5f;
        float y = ((gy + 1.0f) * (float)YD - 1.0f) * 0.5f;
        float z = ((gz + 1.0f) * (float)ZD - 1.0f) * 0.5f;
        float x0f = floorf(x), y0f = floorf(y), z0f = floorf(z);
        int   x0 = (int)x0f,  y0 = (int)y0f,  z0 = (int)z0f;
        float fx = x - x0f,   fy = y - y0f,   fz = z - z0f;
        float wx[2] = {1.0f - fx, fx};
        float wy[2] = {1.0f - fy, fy};
        float wz[2] = {1.0f - fz, fz};
        #pragma unroll
        for (int dz = 0; dz < 2; dz++)
        #pragma unroll
        for (int dy = 0; dy < 2; dy++)
        #pragma unroll
        for (int dx = 0; dx < 2; dx++) {
            int xi = x0 + dx, yi = y0 + dy, zi = z0 + dz;
            bool inb = (xi >= 0) && (xi < XD) && (yi >= 0) && (yi < YD) && (zi >= 0) && (zi < ZD);
            int k = dz*4 + dy*2 + dx;
            s_loff[k] = inb ? ((zi * YD + yi) * XD + xi) : -1;
            s_lw[k]   = wx[dx] * wy[dy] * wz[dz];
        }
    }
    __syncthreads();
    if (threadIdx.x == 0) {
        int cnt = 0;
        #pragma unroll
        for (int n = 0; n < NCAM; n++) cnt += s_valid[n];
        s_rcnt = 1.0f / fmaxf((float)cnt, 1.0f);
    }
    __syncthreads();

    float acc = 0.0f;
    #pragma unroll
    for (int n = 0; n < NCAM; n++) {
        if (s_valid[n]) {
            const float* p = img + (((size_t)(b * NCAM + n) * C_ + c) * (size_t)(HF * WF));
            #pragma unroll
            for (int jj = 0; jj < 4; jj++) {
                int o = s_off[n][jj];
                if (o >= 0) acc += s_w[n][jj] * __ldg(p + o);
            }
        }
    }
    g_feat_cam[bq * C_ + c] = acc * s_rcnt;

    const float* pl = lid + (((size_t)b * C_ + c) * (size_t)(ZD * YD * XD));
    float lacc = 0.0f;
    #pragma unroll
    for (int jj = 0; jj < 8; jj++) {
        int o = s_loff[jj];
        if (o >= 0) lacc += s_lw[jj] * __ldg(pl + o);
    }
    g_feat_lid[bq * C_ + c] = lacc;
}

// ---------------------------------------------------------------------------
// mv256_jb: partial matvec over K=256, j-blocked x2. Thread (jg, ks) owns
// output columns {2jg, 2jg+1} and k rows {c*32 + ks*8 .. +7} per chunk.
// Weight chunks (32 x 256) staged via register-prefetched smem.
// acc[2][QP]: [column][query-pair], packed f32x2 over query pairs.
// ---------------------------------------------------------------------------
__device__ __forceinline__ void mv256_jb(const float* __restrict__ W,
                                         const float* __restrict__ sIn,
                                         float* __restrict__ wbuf,
                                         int jg, int ks, int t, ull acc[2][QP])
{
    const float4* Wv = (const float4*)W;
    float4 r0 = Wv[t], r1 = Wv[512 + t], r2 = Wv[1024 + t], r3 = Wv[1536 + t];
    #pragma unroll 1
    for (int c = 0; c < 8; c++) {
        __syncthreads();                      // wbuf safe to overwrite
        ((float4*)wbuf)[t]        = r0;
        ((float4*)wbuf)[512 + t]  = r1;
        ((float4*)wbuf)[1024 + t] = r2;
        ((float4*)wbuf)[1536 + t] = r3;
        if (c < 7) {
            const float4* Wn = Wv + (size_t)(c + 1) * 2048;
            r0 = Wn[t]; r1 = Wn[512 + t]; r2 = Wn[1024 + t]; r3 = Wn[1536 + t];
        }
        __syncthreads();                      // wbuf visible
        #pragma unroll
        for (int kk = 0; kk < 8; kk++) {
            int krow = ks * 8 + kk;
            ull wp = *(const ull*)&wbuf[krow * 256 + 2 * jg];
            float w0, w1; unpack2(wp, w0, w1);
            ull w20 = packdup(w0), w21 = packdup(w1);
            const float* arow = sIn + (c * 32 + krow) * AST;
            ulonglong2 p0 = *(const ulonglong2*)(arow);
            ulonglong2 p1 = *(const ulonglong2*)(arow + 4);
            ulonglong2 p2 = *(const ulonglong2*)(arow + 8);
            ull        p3 = *(const ull*)(arow + 12);
            fma2(acc[0][0], p0.x, w20); fma2(acc[1][0], p0.x, w21);
            fma2(acc[0][1], p0.y, w20); fma2(acc[1][1], p0.y, w21);
            fma2(acc[0][2], p1.x, w20); fma2(acc[1][2], p1.x, w21);
            fma2(acc[0][3], p1.y, w20); fma2(acc[1][3], p1.y, w21);
            fma2(acc[0][4], p2.x, w20); fma2(acc[1][4], p2.x, w21);
            fma2(acc[0][5], p2.y, w20); fma2(acc[1][5], p2.y, w21);
            fma2(acc[0][6], p3,   w20); fma2(acc[1][6], p3,   w21);
        }
    }
}

// Reduce 4 k-slices into ks==0's acc via sequential smem passes.
__device__ __forceinline__ void reduce4(ull acc[2][QP], ull* sPart, int jg, int ks)
{
    if (ks == 3) {
        #pragma unroll
        for (int jj = 0; jj < 2; jj++)
        #pragma unroll
        for (int qp = 0; qp < QP; qp++)
            sPart[(jg * 2 + jj) * QP + qp] = acc[jj][qp];
    }
    __syncthreads();
    if (ks == 2) {
        #pragma unroll
        for (int jj = 0; jj < 2; jj++)
        #pragma unroll
        for (int qp = 0; qp < QP; qp++) {
            int i = (jg * 2 + jj) * QP + qp;
            sPart[i] = add2(sPart[i], acc[jj][qp]);
        }
    }
    __syncthreads();
    if (ks == 1) {
        #pragma unroll
        for (int jj = 0; jj < 2; jj++)
        #pragma unroll
        for (int qp = 0; qp < QP; qp++) {
            int i = (jg * 2 + jj) * QP + qp;
            sPart[i] = add2(sPart[i], acc[jj][qp]);
        }
    }
    __syncthreads();
    if (ks == 0) {
        #pragma unroll
        for (int jj = 0; jj < 2; jj++)
        #pragma unroll
        for (int qp = 0; qp < QP; qp++)
            acc[jj][qp] = add2(acc[jj][qp], sPart[(jg * 2 + jj) * QP + qp]);
    }
}

// ---------------------------------------------------------------------------
// Kernel 2: fused MLP chain. 512 threads = 128 j-pairs x 4 k-slices.
// Activations in smem transposed [k][q], row stride AST=16 (16B-aligned).
// ---------------------------------------------------------------------------
__global__ void __launch_bounds__(NT, 1)
fuse_kernel(const float* __restrict__ query,
            const float* __restrict__ cam_w,  const float* __restrict__ cam_b,
            const float* __restrict__ lid_w,  const float* __restrict__ lid_b,
            const float* __restrict__ aw1,    const float* __restrict__ ab1,
            const float* __restrict__ aw2,    const float* __restrict__ ab2,
            const float* __restrict__ fw1,    const float* __restrict__ fb1,
            const float* __restrict__ lng,    const float* __restrict__ lnb,
            const float* __restrict__ fw2,    const float* __restrict__ fb2,
            float* __restrict__ out) {
    extern __shared__ float sm[];
    float* B0   = sm;                  // 4096 f : query -> t1
    float* B1   = B0 + C_*AST;         // 4096 f : cam   -> fl
    float* B2   = B1 + C_*AST;         // 4096 f : lid   -> h2
    float* B3   = B2 + C_*AST;         // 4096 f : fc
    float* wbuf = B3 + C_*AST;         // 8192 f : weight chunk (also gate partials)
    ull*   sPart = (ull*)(wbuf + 8192);      // 256*QP ull = 14336B
    float* sHid  = (float*)(sPart + 256*QP); // 64*AST floats
    __shared__ float sWt[TQ][2], sMu[TQ], sRstd[TQ];

    int t  = threadIdx.x;
    int jg = t & 127;                  // j-pair index: columns 2jg, 2jg+1
    int ks = t >> 7;                   // k-slice 0..3
    int qbase = blockIdx.x * TQ;
    int nq = BQ - qbase; if (nq > TQ) nq = TQ;

    // Transposed staging: B0<-query, B1<-cam, B2<-lid ([q][k] -> [k][q])
    for (int i = t; i < nq * C_; i += NT) {
        int q = i >> 8, k = i & 255;
        B0[k*AST + q] = query[(size_t)(qbase+q)*C_ + k];
        B1[k*AST + q] = g_feat_cam[(qbase+q)*C_ + k];
        B2[k*AST + q] = g_feat_lid[(qbase+q)*C_ + k];
    }
    for (int i = nq * C_ + t; i < TQ * C_; i += NT) {
        int q = i >> 8, k = i & 255;
        B0[k*AST+q] = 0.f; B1[k*AST+q] = 0.f; B2[k*AST+q] = 0.f;
    }
    __syncthreads();

    // ---- gate: h = relu(Q @ aw1 + ab1); wt = softmax(h @ aw2 + ab2) ----
    {
        int j4 = t & 63, kh8 = t >> 6;   // 64 cols x 8 k-groups of 32
        ull h[QP];
        #pragma unroll
        for (int qp = 0; qp < QP; qp++) h[qp] = 0;
        for (int kk = 0; kk < 32; kk++) {
            int k = kh8 * 32 + kk;
            ull w2 = packdup(aw1[k*64 + j4]);
            const ull* ap = (const ull*)(B0 + k*AST);
            #pragma unroll
            for (int qp = 0; qp < QP; qp++) fma2(h[qp], ap[qp], w2);
        }
        ull* gred = (ull*)wbuf;
        #pragma unroll
        for (int qp = 0; qp < QP; qp++) gred[(kh8*64 + j4)*QP + qp] = h[qp];
    }
    __syncthreads();
    if (t < 64 * QP) {
        int jj = t / QP, qp = t % QP;
        ull* gred = (ull*)wbuf;
        ull s = gred[jj*QP + qp];
        #pragma unroll
        for (int g8 = 1; g8 < 8; g8++) s = add2(s, gred[(g8*64 + jj)*QP + qp]);
        float lo, hi; unpack2(s, lo, hi);
        float bb = ab1[jj];
        sHid[jj*AST + 2*qp]   = fmaxf(lo + bb, 0.f);
        sHid[jj*AST + 2*qp+1] = fmaxf(hi + bb, 0.f);
    }
    __syncthreads();
    if (t < TQ) {
        float l0 = ab2[0], l1 = ab2[1];
        for (int kk = 0; kk < 64; kk++) {
            float h = sHid[kk*AST + t];
            l0 += h * aw2[kk*2+0];
            l1 += h * aw2[kk*2+1];
        }
        float m  = fmaxf(l0, l1);
        float e0 = expf(l0 - m), e1 = expf(l1 - m);
        float den = e0 + e1;
        sWt[t][0] = e0 / den; sWt[t][1] = e1 / den;
    }
    // (mv256_jb's internal barriers order sWt/gred before reuse)

    // ---- stage A cam: B3 = wt0 * (B1 @ cam_w + cam_b) ----
    {
        ull acc[2][QP];
        #pragma unroll
        for (int jj = 0; jj < 2; jj++)
        #pragma unroll
        for (int qp = 0; qp < QP; qp++) acc[jj][qp] = 0;
        mv256_jb(cam_w, B1, wbuf, jg, ks, t, acc);
        reduce4(acc, sPart, jg, ks);
        if (ks == 0) {
            #pragma unroll
            for (int jj = 0; jj < 2; jj++) {
                int j = 2*jg + jj;
                float bb = cam_b[j];
                #pragma unroll
                for (int qp = 0; qp < QP; qp++) {
                    float lo, hi; unpack2(acc[jj][qp], lo, hi);
                    B3[j*AST + 2*qp]   = sWt[2*qp][0]   * (lo + bb);
                    B3[j*AST + 2*qp+1] = sWt[2*qp+1][0] * (hi + bb);
                }
            }
        }
    }
    // ---- stage A lid: B1 = wt1 * (B2 @ lid_w + lid_b) ----
    {
        ull acc[2][QP];
        #pragma unroll
        for (int jj = 0; jj < 2; jj++)
        #pragma unroll
        for (int qp = 0; qp < QP; qp++) acc[jj][qp] = 0;
        mv256_jb(lid_w, B2, wbuf, jg, ks, t, acc);
        reduce4(acc, sPart, jg, ks);
        if (ks == 0) {
            #pragma unroll
            for (int jj = 0; jj < 2; jj++) {
                int j = 2*jg + jj;
                float bb = lid_b[j];
                #pragma unroll
                for (int qp = 0; qp < QP; qp++) {
                    float lo, hi; unpack2(acc[jj][qp], lo, hi);
                    B1[j*AST + 2*qp]   = sWt[2*qp][1]   * (lo + bb);
                    B1[j*AST + 2*qp+1] = sWt[2*qp+1][1] * (hi + bb);
                }
            }
        }
    }
    // ---- stage E: B0 = fc @ fw1[0:256] + fl @ fw1[256:512] + fb1 ----
    {
        ull acc[2][QP];
        #pragma unroll
        for (int jj = 0; jj < 2; jj++)
        #pragma unroll
        for (int qp = 0; qp < QP; qp++) acc[jj][qp] = 0;
        mv256_jb(fw1,          B3, wbuf, jg, ks, t, acc);
        mv256_jb(fw1 + 256*C_, B1, wbuf, jg, ks, t, acc);
        reduce4(acc, sPart, jg, ks);
        if (ks == 0) {
            #pragma unroll
            for (int jj = 0; jj < 2; jj++) {
                int j = 2*jg + jj;
                float bb = fb1[j];
                #pragma unroll
                for (int qp = 0; qp < QP; qp++) {
                    float lo, hi; unpack2(acc[jj][qp], lo, hi);
                    B0[j*AST + 2*qp]   = lo + bb;
                    B0[j*AST + 2*qp+1] = hi + bb;
                }
            }
        }
    }
    __syncthreads();   // B0 (t1) complete for all threads

    // ---- LayerNorm + relu: B2 = relu(LN(B0)) ----
    {
        int wid = t >> 5, lane = t & 31;
        if (wid < TQ) {
            float s = 0.f;
            #pragma unroll
            for (int i = 0; i < 8; i++) s += B0[(lane + i*32)*AST + wid];
            #pragma unroll
            for (int off = 16; off; off >>= 1) s += __shfl_xor_sync(~0u, s, off);
            float mu = s * (1.0f/256.0f);
            float v = 0.f;
            #pragma unroll
            for (int i = 0; i < 8; i++) {
                float d = B0[(lane + i*32)*AST + wid] - mu;
                v += d * d;
            }
            #pragma unroll
            for (int off = 16; off; off >>= 1) v += __shfl_xor_sync(~0u, v, off);
            if (lane == 0) { sMu[wid] = mu; sRstd[wid] = rsqrtf(v*(1.0f/256.0f) + 1e-5f); }
        }
    }
    __syncthreads();
    {
        int k0 = t & 255, qh = t >> 8;
        float g = lng[k0], bb = lnb[k0];
        #pragma unroll
        for (int q = qh*QP; q < qh*QP + QP; q++) {
            float v = (B0[k0*AST + q] - sMu[q]) * sRstd[q] * g + bb;
            B2[k0*AST + q] = fmaxf(v, 0.f);
        }
    }

    // ---- stage G: out = h2 @ fw2 + fb2 ----
    {
        ull acc[2][QP];
        #pragma unroll
        for (int jj = 0; jj < 2; jj++)
        #pragma unroll
        for (int qp = 0; qp < QP; qp++) acc[jj][qp] = 0;
        mv256_jb(fw2, B2, wbuf, jg, ks, t, acc);
        reduce4(acc, sPart, jg, ks);
        if (ks == 0) {
            #pragma unroll
            for (int jj = 0; jj < 2; jj++) {
                int j = 2*jg + jj;
                float bb = fb2[j];
                #pragma unroll
                for (int qp = 0; qp < QP; qp++) {
                    float lo, hi; unpack2(acc[jj][qp], lo, hi);
                    int q0 = 2*qp;
                    if (q0 < nq)     out[(size_t)(qbase+q0)*C_ + j]   = lo + bb;
                    if (q0 + 1 < nq) out[(size_t)(qbase+q0+1)*C_ + j] = hi + bb;
                }
            }
        }
    }
}

// ---------------------------------------------------------------------------
extern "C" void kernel_launch(void* const* d_in, const int* in_sizes, int n_in,
                              void* d_out, int out_size) {
    const float* query = (const float*)d_in[0];
    const float* rp    = (const float*)d_in[1];
    const float* img   = (const float*)d_in[2];
    const float* lid   = (const float*)d_in[3];
    const float* l2i   = (const float*)d_in[4];
    const float* cam_w = (const float*)d_in[5];
    const float* cam_b = (const float*)d_in[6];
    const float* lid_w = (const float*)d_in[7];
    const float* lid_b = (const float*)d_in[8];
    const float* aw1   = (const float*)d_in[9];
    const float* ab1   = (const float*)d_in[10];
    const float* aw2   = (const float*)d_in[11];
    const float* ab2   = (const float*)d_in[12];
    const float* fw1   = (const float*)d_in[13];
    const float* fb1   = (const float*)d_in[14];
    const float* lng   = (const float*)d_in[15];
    const float* lnb   = (const float*)d_in[16];
    const float* fw2   = (const float*)d_in[17];
    const float* fb2   = (const float*)d_in[18];
    float* out = (float*)d_out;

    sample_kernel<<<BQ, 256>>>(rp, img, lid, l2i);

    size_t smem = (size_t)(4*C_*AST + 8192) * sizeof(float)
                + (size_t)(256*QP) * sizeof(ull)
                + (size_t)(64*AST) * sizeof(float);
    cudaFuncSetAttribute(fuse_kernel, cudaFuncAttributeMaxDynamicSharedMemorySize, (int)smem);
    fuse_kernel<<<NBLK, NT, smem>>>(query,
                                    cam_w, cam_b, lid_w, lid_b,
                                    aw1, ab1, aw2, ab2,
                                    fw1, fb1, lng, lnb, fw2, fb2,
                                    out);
}